// round 3
// baseline (speedup 1.0000x reference)
#include <cuda_runtime.h>
#include <math.h>

#define KK 10
#define NN 96
#define TT 40
#define HD 48
#define NROW 960          // K*N
#define NBINS 36
#define RPB 4             // rows per block in step kernel
#define STPB 144          // threads per block in step kernel

// -------- device scratch (static allocation only; no cudaMalloc allowed) ----
__device__ __align__(16) float g_out1[16*80*80];
__device__ __align__(16) float g_fmap[32*80*80];
__device__ __align__(16) float g_xpre[TT*NROW*48];       // [t][row][c<48]: feat(32)+fv(16)
__device__ int   g_nbcnt[TT*NROW];                        // #nonzero bins per (t,row)
__device__ int   g_nbbin[TT*NROW*NBINS];                  // (bin<<16)|winner
__device__ float g_nbinv[TT*NROW*NBINS];                  // 1/count
__device__ __align__(16) float g_h[2][NROW*HD];           // double-buffered hidden state
__device__ float g_score[NROW];
__device__ __align__(16) float g_wihT[96*144];            // transposed gru_wih
__device__ __align__(16) float g_whhT[48*144];            // transposed gru_whh
__device__ __align__(16) float g_scfT[1728*48];           // transposed fcscf_w

// ---------------------------------------------------------------------------
// conv1: img (1,4,160,160) -> out1 (16,80,80), stride 2, pad 2, k=5, relu
__global__ void k_conv1(const float* __restrict__ img,
                        const float* __restrict__ w1,
                        const float* __restrict__ b1) {
    int idx = blockIdx.x * blockDim.x + threadIdx.x;
    if (idx >= 16*80*80) return;
    int ox = idx % 80;
    int oy = (idx / 80) % 80;
    int oc = idx / 6400;
    float acc = b1[oc];
    int iy0 = oy*2 - 2, ix0 = ox*2 - 2;
    for (int ic = 0; ic < 4; ic++) {
        #pragma unroll
        for (int ky = 0; ky < 5; ky++) {
            int iy = iy0 + ky;
            if ((unsigned)iy >= 160u) continue;
            #pragma unroll
            for (int kx = 0; kx < 5; kx++) {
                int ix = ix0 + kx;
                if ((unsigned)ix >= 160u) continue;
                acc = fmaf(__ldg(&img[(ic*160 + iy)*160 + ix]),
                           __ldg(&w1[((oc*4 + ic)*5 + ky)*5 + kx]), acc);
            }
        }
    }
    g_out1[idx] = fmaxf(acc, 0.f);
}

// conv2: out1 (16,80,80) -> fmap (32,80,80), stride 1, pad 2, k=5, relu
// tiled: one block = one oc x 16x16 output tile, input halo in shared
__global__ void k_conv2(const float* __restrict__ w2,
                        const float* __restrict__ b2) {
    __shared__ float in_s[16*20*20];   // 16 ic, 20x20 halo tile
    __shared__ float w_s[400];         // 16*5*5 for this oc
    int oc  = blockIdx.z;
    int ty0 = blockIdx.y * 16;
    int tx0 = blockIdx.x * 16;
    int tid = threadIdx.x;             // 256 threads

    for (int i = tid; i < 400; i += 256) w_s[i] = w2[oc*400 + i];
    for (int i = tid; i < 16*400; i += 256) {
        int ic  = i / 400;
        int rem = i % 400;
        int yy  = rem / 20, xx = rem % 20;
        int gy  = ty0 - 2 + yy, gx = tx0 - 2 + xx;
        in_s[i] = (gy >= 0 && gy < 80 && gx >= 0 && gx < 80)
                  ? g_out1[(ic*80 + gy)*80 + gx] : 0.f;
    }
    __syncthreads();

    int lx = tid % 16, ly = tid / 16;
    float acc = b2[oc];
    for (int ic = 0; ic < 16; ic++) {
        #pragma unroll
        for (int ky = 0; ky < 5; ky++) {
            #pragma unroll
            for (int kx = 0; kx < 5; kx++) {
                acc = fmaf(in_s[ic*400 + (ly + ky)*20 + (lx + kx)],
                           w_s[(ic*5 + ky)*5 + kx], acc);
            }
        }
    }
    g_fmap[(oc*80 + ty0 + ly)*80 + tx0 + lx] = fmaxf(acc, 0.f);
}

// ---------------------------------------------------------------------------
// prep: weight transposes + h0 init (tile hx) + zero score
#define SEG0 (1728*48)           // scfT        82944
#define SEG1 (SEG0 + 96*144)     // wihT       +13824
#define SEG2 (SEG1 + 48*144)     // whhT       + 6912
#define SEG3 (SEG2 + NROW*HD)    // h0         +46080
#define SEG4 (SEG3 + NROW)       // score      +  960
__global__ void k_prep(const float* __restrict__ hx,
                       const float* __restrict__ wih,
                       const float* __restrict__ whh,
                       const float* __restrict__ scfw) {
    int i = blockIdx.x * blockDim.x + threadIdx.x;
    if (i < SEG0) {
        int in = i / 48, o = i % 48;
        g_scfT[i] = scfw[o*1728 + in];
    } else if (i < SEG1) {
        int j = i - SEG0;
        int c = j / 144, g = j % 144;
        g_wihT[j] = wih[g*96 + c];
    } else if (i < SEG2) {
        int j = i - SEG1;
        int c = j / 144, g = j % 144;
        g_whhT[j] = whh[g*48 + c];
    } else if (i < SEG3) {
        int j = i - SEG2;
        g_h[0][j] = hx[j % (NN*HD)];   // tile(hx, (K,1))
    } else if (i < SEG4) {
        g_score[i - SEG3] = 0.f;
    }
}

// ---------------------------------------------------------------------------
// x_pre: feat gather (32) + velocity-fc relu (16) for all (t,k,n)
__global__ void k_xpre(const float* __restrict__ ypath,
                       const float* __restrict__ curloc,
                       const float* __restrict__ fvw,
                       const float* __restrict__ fvb) {
    int idx = blockIdx.x * blockDim.x + threadIdx.x;
    if (idx >= TT*NROW*48) return;
    int c    = idx % 48;
    int rowg = idx / 48;              // t*960 + k*96 + n
    int t    = rowg / NROW;
    int kn   = rowg % NROW;
    int k    = kn / NN, n = kn % NN;
    const float* yp = ypath + ((size_t)(k*TT + t)*NN + n)*2;
    float out;
    if (c < 32) {
        float lx = yp[0], ly = yp[1];
        int ui = 40 - (int)ly;        // trunc-toward-zero matches astype(int32)
        int vi = 40 - (int)lx;
        ui = min(max(ui, 0), 79);
        vi = min(max(vi, 0), 79);
        out = g_fmap[c*6400 + ui*80 + vi];
    } else {
        int f = c - 32;
        float px, py;
        if (t == 0) { px = curloc[n*2]; py = curloc[n*2 + 1]; }
        else {
            const float* pp = ypath + ((size_t)(k*TT + (t - 1))*NN + n)*2;
            px = pp[0]; py = pp[1];
        }
        float vx = (yp[0] - px) * 10.f;
        float vy = (yp[1] - py) * 10.f;
        out = fmaxf(fmaf(vx, fvw[f*2], fmaf(vy, fvw[f*2 + 1], fvb[f])), 0.f);
    }
    g_xpre[(size_t)rowg*48 + c] = out;
}

// ---------------------------------------------------------------------------
// binning: per (t,k,i) build compact list of (bin, winner=max j, 1/count)
__global__ void k_bins(const float* __restrict__ ypath) {
    int idx = blockIdx.x * blockDim.x + threadIdx.x;
    if (idx >= TT*NROW) return;
    int t  = idx / NROW;
    int kn = idx % NROW;
    int k  = kn / NN, i = kn % NN;
    const float* locb = ypath + (size_t)(k*TT + t)*NN*2;
    float xi = locb[i*2], yi = locb[i*2 + 1];

    const float R0f = 0.5f, R1f = 4.0f;
    const float RSTEPf = (float)((4.0 - 0.5)/6.0);
    const float TSTEPf = (float)(2.0*3.14159265358979323846/6.0);
    const float TWOPIf = (float)(2.0*3.14159265358979323846);

    int winner[NBINS];
    int cnt[NBINS];
    #pragma unroll
    for (int b = 0; b < NBINS; b++) { winner[b] = -1; cnt[b] = 0; }

    for (int j = 0; j < NN; j++) {
        if (j == i) continue;
        float cx = locb[j*2]     - xi;
        float cy = locb[j*2 + 1] - yi;
        float dist = __fsqrt_rn(fmaf(cx, cx, cy*cy));
        if (dist < R0f || dist > R1f) continue;
        float dsafe = fmaxf(dist, 1e-10f);
        float cost  = fminf(fmaxf(__fdiv_rn(cx, dsafe), -1.f), 1.f);
        float ac    = acosf(cost);
        float theta = (cy < 0.f) ? (TWOPIf - ac) : ac;
        int ub = (int)__fdiv_rn(dist - R0f, RSTEPf);
        ub = min(max(ub, 0), 5);
        int vb = (int)__fdiv_rn(theta, TSTEPf);
        vb = min(max(vb, 0), 5);
        int b = ub*6 + vb;
        winner[b] = j;            // ascending j: last write == max j
        cnt[b]++;
    }
    int nb = 0;
    int base = idx * NBINS;
    for (int b = 0; b < NBINS; b++) {
        if (winner[b] >= 0) {
            g_nbbin[base + nb] = (b << 16) | winner[b];
            g_nbinv[base + nb] = __fdiv_rn(1.f, (float)cnt[b]);
            nb++;
        }
    }
    g_nbcnt[idx] = nb;
}

// ---------------------------------------------------------------------------
// one GRU scan step: rhalf (sparse social pooling) + GRU + score accumulation
__global__ void __launch_bounds__(STPB) k_step(int t,
        const float* __restrict__ scfb,
        const float* __restrict__ bih,
        const float* __restrict__ bhh,
        const float* __restrict__ wsc) {
    __shared__ __align__(16) float hsh[NN*HD];      // hidden = h_prev rows 0..95
    __shared__ __align__(16) float hown[HD*RPB];    // [h][r]
    __shared__ __align__(16) float xs[96*RPB];      // [c][r]
    __shared__ __align__(16) float gis[144*RPB];    // [g][r]
    __shared__ __align__(16) float ghs[144*RPB];    // [g][r]
    __shared__ float hns[RPB*HD];                   // [r][h]

    const int tid  = threadIdx.x;
    const int row0 = blockIdx.x * RPB;
    const float* __restrict__ hprev = g_h[t & 1];
    float* __restrict__ hnext       = g_h[(t + 1) & 1];

    for (int i = tid; i < NN*HD/4; i += STPB)
        reinterpret_cast<float4*>(hsh)[i] =
            reinterpret_cast<const float4*>(hprev)[i];
    for (int i = tid; i < HD*RPB; i += STPB) {
        int r = i % RPB, h = i / RPB;
        hown[i] = hprev[(row0 + r)*HD + h];
    }
    __syncthreads();

    if (tid >= 48) {   // stage precomputed lhalf into xs[c][r]
        for (int i = tid - 48; i < 48*RPB; i += (STPB - 48)) {
            int c = i / RPB, r = i % RPB;
            xs[c*RPB + r] = g_xpre[(size_t)(t*NROW + row0 + r)*48 + c];
        }
    } else {           // rhalf: sparse fcscf over nonzero bins
        const int o = tid;
        for (int r = 0; r < RPB; r++) {
            int base = t*NROW + row0 + r;
            int nb = g_nbcnt[base];
            const int*   bb = g_nbbin + base*NBINS;
            const float* iv = g_nbinv + base*NBINS;
            float acc = scfb[o];
            for (int e = 0; e < nb; e++) {
                int pk    = bb[e];
                float inv = iv[e];
                int bin = pk >> 16;
                int w   = pk & 0xffff;
                const float* __restrict__ wp = g_scfT + bin*48*48 + o;
                const float* hp = hsh + w*HD;
                float a2 = 0.f;
                #pragma unroll
                for (int h = 0; h < 48; h++)
                    a2 = fmaf(wp[h*48], hp[h], a2);
                acc = fmaf(inv, a2, acc);
            }
            xs[(48 + o)*RPB + r] = fmaxf(acc, 0.f);
        }
    }
    __syncthreads();

    {   // gi (96-dot) and gh (48-dot) for 4 rows, thread g in [0,144)
        const int g = tid;
        float a0, a1, a2, a3;
        float b = bih[g];
        a0 = a1 = a2 = a3 = b;
        #pragma unroll 4
        for (int c = 0; c < 96; c++) {
            float w = g_wihT[c*144 + g];
            float4 xv = reinterpret_cast<const float4*>(xs)[c];
            a0 = fmaf(w, xv.x, a0);
            a1 = fmaf(w, xv.y, a1);
            a2 = fmaf(w, xv.z, a2);
            a3 = fmaf(w, xv.w, a3);
        }
        reinterpret_cast<float4*>(gis)[g] = make_float4(a0, a1, a2, a3);

        float bh = bhh[g];
        a0 = a1 = a2 = a3 = bh;
        #pragma unroll 4
        for (int c = 0; c < 48; c++) {
            float w = g_whhT[c*144 + g];
            float4 hv = reinterpret_cast<const float4*>(hown)[c];
            a0 = fmaf(w, hv.x, a0);
            a1 = fmaf(w, hv.y, a1);
            a2 = fmaf(w, hv.z, a2);
            a3 = fmaf(w, hv.w, a3);
        }
        reinterpret_cast<float4*>(ghs)[g] = make_float4(a0, a1, a2, a3);
    }
    __syncthreads();

    for (int task = tid; task < RPB*48; task += STPB) {
        int r = task / 48, o = task % 48;
        float gir = gis[o*RPB + r];
        float giz = gis[(48 + o)*RPB + r];
        float gin = gis[(96 + o)*RPB + r];
        float ghr = ghs[o*RPB + r];
        float ghz = ghs[(48 + o)*RPB + r];
        float ghn = ghs[(96 + o)*RPB + r];
        float rg = 1.f / (1.f + expf(-(gir + ghr)));
        float zg = 1.f / (1.f + expf(-(giz + ghz)));
        float ng = tanhf(fmaf(rg, ghn, gin));
        float hold = hown[o*RPB + r];
        float hn = fmaf(zg, hold, (1.f - zg)*ng);
        hnext[(row0 + r)*HD + o] = hn;
        hns[r*HD + o] = hn;
    }
    __syncthreads();

    if (tid < RPB) {   // score += h_new . w_score (deterministic order)
        float s = 0.f;
        for (int h = 0; h < HD; h++) s = fmaf(hns[tid*HD + h], wsc[h], s);
        g_score[row0 + tid] += s;
    }
}

// ---------------------------------------------------------------------------
// finalize: delta_y (K,T,N,2) then score (K,N,1) into d_out
__global__ void k_final(float* __restrict__ out,
                        const float* __restrict__ dyw,
                        const float* __restrict__ dyb,
                        const float* __restrict__ bsc) {
    int idx = blockIdx.x * blockDim.x + threadIdx.x;
    const int NDY = KK*TT*NN*2;   // 76800
    if (idx < NDY) {
        int c = idx % 2;
        int n = (idx / 2) % NN;
        int t = (idx / (2*NN)) % TT;
        int k = idx / (2*NN*TT);
        int row = k*NN + n;
        int od  = c*TT + t;
        const float* hl = &g_h[0][row*HD];     // after 40 steps state is in buf 0
        const float* wr = &dyw[od*HD];
        float acc = dyb[od];
        #pragma unroll 8
        for (int h = 0; h < HD; h++) acc = fmaf(hl[h], wr[h], acc);
        out[idx] = fmaxf(acc, 0.f);
    } else if (idx < NDY + NROW) {
        int r = idx - NDY;
        out[idx] = g_score[r] + (float)TT * bsc[0];
    }
}

// ---------------------------------------------------------------------------
extern "C" void kernel_launch(void* const* d_in, const int* in_sizes, int n_in,
                              void* d_out, int out_size) {
    const float* hx    = (const float*)d_in[0];
    const float* cur   = (const float*)d_in[1];
    const float* ypath = (const float*)d_in[2];
    const float* img   = (const float*)d_in[3];
    const float* c1w   = (const float*)d_in[4];
    const float* c1b   = (const float*)d_in[5];
    const float* c2w   = (const float*)d_in[6];
    const float* c2b   = (const float*)d_in[7];
    const float* fvw   = (const float*)d_in[8];
    const float* fvb   = (const float*)d_in[9];
    const float* wih   = (const float*)d_in[10];
    const float* whh   = (const float*)d_in[11];
    const float* bih   = (const float*)d_in[12];
    const float* bhh   = (const float*)d_in[13];
    const float* scfw  = (const float*)d_in[14];
    const float* scfb  = (const float*)d_in[15];
    const float* wsc   = (const float*)d_in[16];
    const float* bsc   = (const float*)d_in[17];
    const float* dyw   = (const float*)d_in[18];
    const float* dyb   = (const float*)d_in[19];
    float* out = (float*)d_out;

    k_conv1<<<(16*80*80 + 255)/256, 256>>>(img, c1w, c1b);
    k_conv2<<<dim3(5, 5, 32), 256>>>(c2w, c2b);
    k_prep<<<(SEG4 + 255)/256, 256>>>(hx, wih, whh, scfw);
    k_xpre<<<(TT*NROW*48 + 255)/256, 256>>>(ypath, cur, fvw, fvb);
    k_bins<<<(TT*NROW + 255)/256, 256>>>(ypath);
    for (int t = 0; t < TT; t++)
        k_step<<<NROW/RPB, STPB>>>(t, scfb, bih, bhh, wsc);
    k_final<<<(KK*TT*NN*2 + NROW + 255)/256, 256>>>(out, dyw, dyb, bsc);
}

// round 4
// speedup vs baseline: 1.0979x; 1.0979x over previous
#include <cuda_runtime.h>
#include <math.h>

#define KK 10
#define NN 96
#define TT 40
#define HD 48
#define NROW 960          // K*N
#define NBINS 36
#define NBLK 120          // persistent grid: one wave (<=148 SMs)
#define RPB 8             // rows per block (120*8 = 960)
#define NTHR 256

// -------- device scratch (static allocation only) ---------------------------
__device__ __align__(16) float g_out1[16*80*80];
__device__ __align__(16) float g_fmapT[80*80*32];        // [pix][c] transposed
__device__ __align__(16) float g_xpre[TT*NROW*48];       // [t][row][c]: feat(32)+fv(16)
__device__ int   g_nbcnt[TT*NROW];
__device__ int   g_nbbin[TT*NROW*NBINS];                  // (bin<<16)|winner
__device__ float g_nbinv[TT*NROW*NBINS];                  // 1/count
__device__ __align__(16) float g_h[2][NROW*HD];           // double-buffered hidden
__device__ __align__(16) float g_proj[NN*1728];           // [j][bin*48+o]
__device__ __align__(16) float g_wihT[96*144];
__device__ __align__(16) float g_whhT[48*144];
__device__ __align__(16) float g_scfT[1728*48];           // [bin*48+h][o]

// -------- grid-wide sense barrier (single-wave persistent kernel) -----------
__device__ unsigned g_bar_count = 0;
__device__ volatile unsigned g_bar_gen = 0;

__device__ __forceinline__ void gsync() {
    __syncthreads();
    if (threadIdx.x == 0) {
        unsigned gen = g_bar_gen;
        __threadfence();
        if (atomicAdd(&g_bar_count, 1u) == NBLK - 1) {
            g_bar_count = 0;
            __threadfence();
            g_bar_gen = gen + 1;
        } else {
            while (g_bar_gen == gen) { }
        }
        __threadfence();
    }
    __syncthreads();
}

// ---------------------------------------------------------------------------
// conv1: img (1,4,160,160) -> out1 (16,80,80), stride 2, pad 2, k=5, relu
__global__ void k_conv1(const float* __restrict__ img,
                        const float* __restrict__ w1,
                        const float* __restrict__ b1) {
    int idx = blockIdx.x * blockDim.x + threadIdx.x;
    if (idx >= 16*80*80) return;
    int ox = idx % 80;
    int oy = (idx / 80) % 80;
    int oc = idx / 6400;
    float acc = b1[oc];
    int iy0 = oy*2 - 2, ix0 = ox*2 - 2;
    for (int ic = 0; ic < 4; ic++) {
        #pragma unroll
        for (int ky = 0; ky < 5; ky++) {
            int iy = iy0 + ky;
            if ((unsigned)iy >= 160u) continue;
            #pragma unroll
            for (int kx = 0; kx < 5; kx++) {
                int ix = ix0 + kx;
                if ((unsigned)ix >= 160u) continue;
                acc = fmaf(__ldg(&img[(ic*160 + iy)*160 + ix]),
                           __ldg(&w1[((oc*4 + ic)*5 + ky)*5 + kx]), acc);
            }
        }
    }
    g_out1[idx] = fmaxf(acc, 0.f);
}

// conv2: out1 (16,80,80) -> fmapT (80*80,32), stride 1, pad 2, k=5, relu
__global__ void k_conv2(const float* __restrict__ w2,
                        const float* __restrict__ b2) {
    __shared__ float in_s[16*20*20];
    __shared__ float w_s[400];
    int oc  = blockIdx.z;
    int ty0 = blockIdx.y * 16;
    int tx0 = blockIdx.x * 16;
    int tid = threadIdx.x;

    for (int i = tid; i < 400; i += 256) w_s[i] = w2[oc*400 + i];
    for (int i = tid; i < 16*400; i += 256) {
        int ic  = i / 400;
        int rem = i % 400;
        int yy  = rem / 20, xx = rem % 20;
        int gy  = ty0 - 2 + yy, gx = tx0 - 2 + xx;
        in_s[i] = (gy >= 0 && gy < 80 && gx >= 0 && gx < 80)
                  ? g_out1[(ic*80 + gy)*80 + gx] : 0.f;
    }
    __syncthreads();

    int lx = tid % 16, ly = tid / 16;
    float acc = b2[oc];
    for (int ic = 0; ic < 16; ic++) {
        #pragma unroll
        for (int ky = 0; ky < 5; ky++) {
            #pragma unroll
            for (int kx = 0; kx < 5; kx++) {
                acc = fmaf(in_s[ic*400 + (ly + ky)*20 + (lx + kx)],
                           w_s[(ic*5 + ky)*5 + kx], acc);
            }
        }
    }
    g_fmapT[((ty0 + ly)*80 + tx0 + lx)*32 + oc] = fmaxf(acc, 0.f);
}

// ---------------------------------------------------------------------------
// prep: weight transposes + h0 init (tile hx)
#define SEG0 (1728*48)           // scfT
#define SEG1 (SEG0 + 96*144)     // wihT
#define SEG2 (SEG1 + 48*144)     // whhT
#define SEG3 (SEG2 + NROW*HD)    // h0
__global__ void k_prep(const float* __restrict__ hx,
                       const float* __restrict__ wih,
                       const float* __restrict__ whh,
                       const float* __restrict__ scfw) {
    int i = blockIdx.x * blockDim.x + threadIdx.x;
    if (i < SEG0) {
        int in = i / 48, o = i % 48;
        g_scfT[i] = scfw[o*1728 + in];
    } else if (i < SEG1) {
        int j = i - SEG0;
        int c = j / 144, g = j % 144;
        g_wihT[j] = wih[g*96 + c];
    } else if (i < SEG2) {
        int j = i - SEG1;
        int c = j / 144, g = j % 144;
        g_whhT[j] = whh[g*48 + c];
    } else if (i < SEG3) {
        int j = i - SEG2;
        g_h[0][j] = hx[j % (NN*HD)];
    }
}

// ---------------------------------------------------------------------------
// x_pre: one thread per (t,row): feat gather (32, coalesced 128B) + vel-fc (16)
__global__ void k_xpre(const float* __restrict__ ypath,
                       const float* __restrict__ curloc,
                       const float* __restrict__ fvw,
                       const float* __restrict__ fvb) {
    int idx = blockIdx.x * blockDim.x + threadIdx.x;
    if (idx >= TT*NROW) return;
    int t  = idx / NROW;
    int kn = idx % NROW;
    int k  = kn / NN, n = kn % NN;
    const float* yp = ypath + ((size_t)(k*TT + t)*NN + n)*2;
    float lx = yp[0], ly = yp[1];
    int ui = 40 - (int)ly;   // trunc-toward-zero matches astype(int32)
    int vi = 40 - (int)lx;
    ui = min(max(ui, 0), 79);
    vi = min(max(vi, 0), 79);
    const float4* fp = (const float4*)(g_fmapT + (ui*80 + vi)*32);
    float4* xp = (float4*)(g_xpre + (size_t)idx*48);
    #pragma unroll
    for (int q = 0; q < 8; q++) xp[q] = fp[q];

    float px, py;
    if (t == 0) { px = curloc[n*2]; py = curloc[n*2 + 1]; }
    else {
        const float* pp = ypath + ((size_t)(k*TT + t - 1)*NN + n)*2;
        px = pp[0]; py = pp[1];
    }
    float vx = (lx - px) * 10.f;
    float vy = (ly - py) * 10.f;
    float* xo = g_xpre + (size_t)idx*48 + 32;
    #pragma unroll
    for (int f = 0; f < 16; f++)
        xo[f] = fmaxf(fmaf(vx, fvw[f*2], fmaf(vy, fvw[f*2 + 1], fvb[f])), 0.f);
}

// ---------------------------------------------------------------------------
// binning: per (t,k,i) compact list of (bin, winner=max j, 1/count)
__global__ void k_bins(const float* __restrict__ ypath) {
    int idx = blockIdx.x * blockDim.x + threadIdx.x;
    if (idx >= TT*NROW) return;
    int t  = idx / NROW;
    int kn = idx % NROW;
    int k  = kn / NN, i = kn % NN;
    const float* locb = ypath + (size_t)(k*TT + t)*NN*2;
    float xi = locb[i*2], yi = locb[i*2 + 1];

    const float R0f = 0.5f, R1f = 4.0f;
    const float RSTEPf = (float)((4.0 - 0.5)/6.0);
    const float TSTEPf = (float)(2.0*3.14159265358979323846/6.0);
    const float TWOPIf = (float)(2.0*3.14159265358979323846);

    int winner[NBINS];
    int cnt[NBINS];
    #pragma unroll
    for (int b = 0; b < NBINS; b++) { winner[b] = -1; cnt[b] = 0; }

    for (int j = 0; j < NN; j++) {
        if (j == i) continue;
        float cx = locb[j*2]     - xi;
        float cy = locb[j*2 + 1] - yi;
        float dist = __fsqrt_rn(fmaf(cx, cx, cy*cy));
        if (dist < R0f || dist > R1f) continue;
        float dsafe = fmaxf(dist, 1e-10f);
        float cost  = fminf(fmaxf(__fdiv_rn(cx, dsafe), -1.f), 1.f);
        float ac    = acosf(cost);
        float theta = (cy < 0.f) ? (TWOPIf - ac) : ac;
        int ub = (int)__fdiv_rn(dist - R0f, RSTEPf);
        ub = min(max(ub, 0), 5);
        int vb = (int)__fdiv_rn(theta, TSTEPf);
        vb = min(max(vb, 0), 5);
        int b = ub*6 + vb;
        winner[b] = j;
        cnt[b]++;
    }
    int nb = 0;
    int base = idx * NBINS;
    for (int b = 0; b < NBINS; b++) {
        if (winner[b] >= 0) {
            g_nbbin[base + nb] = (b << 16) | winner[b];
            g_nbinv[base + nb] = __fdiv_rn(1.f, (float)cnt[b]);
            nb++;
        }
    }
    g_nbcnt[idx] = nb;
}

// ---------------------------------------------------------------------------
// persistent kernel: all 40 GRU steps + epilogue (delta_y, score)
__global__ void __launch_bounds__(NTHR, 1) k_steps(
        const float* __restrict__ scfb,
        const float* __restrict__ bih,
        const float* __restrict__ bhh,
        const float* __restrict__ wsc,
        const float* __restrict__ dyw,
        const float* __restrict__ dyb,
        const float* __restrict__ bsc,
        float* __restrict__ out) {
    __shared__ __align__(16) float sW[48*48];      // phase A: bin weight slice
    __shared__ __align__(16) float sHid[32*48];    // phase A: hidden row slice
    __shared__ __align__(16) float xs[96][RPB];    // [c][r]
    __shared__ __align__(16) float hown[48][RPB];  // [h][r]
    __shared__ __align__(16) float gis[144][RPB];
    __shared__ __align__(16) float ghs[144][RPB];
    __shared__ __align__(16) float hns[RPB][48];
    __shared__ float s_score[RPB];

    const int tid  = threadIdx.x;
    const int blk  = blockIdx.x;
    const int row0 = blk * RPB;
    const int binA  = blk / 3;     // phase A role (blk < 108)
    const int partA = blk % 3;

    if (tid < RPB) s_score[tid] = 0.f;

    for (int t = 0; t < TT; t++) {
        gsync();  // h(t) fully visible
        const float* __restrict__ hprev = g_h[t & 1];
        float* __restrict__ hnext       = g_h[(t + 1) & 1];

        // ===== phase A: proj slice = hidden[32 rows] @ W_bin (blocks 0..107)
        if (blk < 108) {
            const float4* wsrc = (const float4*)(g_scfT + binA*48*48);
            for (int i = tid; i < 576; i += NTHR)
                ((float4*)sW)[i] = wsrc[i];
            const float4* hsrc = (const float4*)(hprev + partA*32*48);
            for (int i = tid; i < 384; i += NTHR)
                ((float4*)sHid)[i] = hsrc[i];
            __syncthreads();
            for (int idx = tid; idx < 32*48; idx += NTHR) {
                int j = idx / 48, o = idx % 48;
                const float* hp = sHid + j*48;
                float acc = 0.f;
                #pragma unroll
                for (int h = 0; h < 48; h++)
                    acc = fmaf(sW[h*48 + o], hp[h], acc);
                g_proj[(partA*32 + j)*1728 + binA*48 + o] = acc;
            }
        }

        // ===== phase B prelim (independent of proj)
        for (int i = tid; i < 48*RPB; i += NTHR) {
            int h = i / RPB, r = i % RPB;
            hown[h][r] = hprev[(row0 + r)*HD + h];
        }
        for (int i = tid; i < 48*RPB; i += NTHR) {
            int c = i / RPB, r = i % RPB;
            xs[c][r] = g_xpre[(size_t)(t*NROW + row0 + r)*48 + c];
        }
        __syncthreads();

        // gh GEMM: 288 tasks (g, half-of-8-rows)
        for (int task = tid; task < 288; task += NTHR) {
            int g = task >> 1, half = task & 1;
            float b = bhh[g];
            float4 acc = make_float4(b, b, b, b);
            #pragma unroll 4
            for (int c = 0; c < 48; c++) {
                float w = __ldg(&g_whhT[c*144 + g]);
                float4 hv = ((const float4*)(&hown[c][0]))[half];
                acc.x = fmaf(w, hv.x, acc.x);
                acc.y = fmaf(w, hv.y, acc.y);
                acc.z = fmaf(w, hv.z, acc.z);
                acc.w = fmaf(w, hv.w, acc.w);
            }
            ((float4*)(&ghs[g][0]))[half] = acc;
        }

        gsync();  // proj(t) ready everywhere

        // ===== rhalf gather: 8 rows x 48 outputs
        #pragma unroll
        for (int pass = 0; pass < 2; pass++) {
            int r = pass*4 + (tid >> 6);
            int o = tid & 63;
            if (o < 48) {
                int base = t*NROW + row0 + r;
                int nb = g_nbcnt[base];
                const int*   bb = g_nbbin + base*NBINS;
                const float* iv = g_nbinv + base*NBINS;
                float acc = scfb[o];
                for (int e = 0; e < nb; e++) {
                    int pk    = bb[e];
                    float inv = iv[e];
                    int b = pk >> 16, w = pk & 0xffff;
                    acc = fmaf(inv, g_proj[w*1728 + b*48 + o], acc);
                }
                xs[48 + o][r] = fmaxf(acc, 0.f);
            }
        }
        __syncthreads();

        // gi GEMM: 288 tasks
        for (int task = tid; task < 288; task += NTHR) {
            int g = task >> 1, half = task & 1;
            float b = bih[g];
            float4 acc = make_float4(b, b, b, b);
            #pragma unroll 4
            for (int c = 0; c < 96; c++) {
                float w = __ldg(&g_wihT[c*144 + g]);
                float4 xv = ((const float4*)(&xs[c][0]))[half];
                acc.x = fmaf(w, xv.x, acc.x);
                acc.y = fmaf(w, xv.y, acc.y);
                acc.z = fmaf(w, xv.z, acc.z);
                acc.w = fmaf(w, xv.w, acc.w);
            }
            ((float4*)(&gis[g][0]))[half] = acc;
        }
        __syncthreads();

        // GRU elementwise: 384 tasks
        for (int task = tid; task < RPB*48; task += NTHR) {
            int r = task / 48, o = task % 48;
            float gir = gis[o][r],      ghr = ghs[o][r];
            float giz = gis[48 + o][r], ghz = ghs[48 + o][r];
            float gin = gis[96 + o][r], ghn = ghs[96 + o][r];
            float rg = 1.f / (1.f + expf(-(gir + ghr)));
            float zg = 1.f / (1.f + expf(-(giz + ghz)));
            float ng = tanhf(fmaf(rg, ghn, gin));
            float hold = hown[o][r];
            float hn = fmaf(zg, hold, (1.f - zg)*ng);
            hnext[(row0 + r)*HD + o] = hn;
            hns[r][o] = hn;
        }
        __syncthreads();

        if (tid < RPB) {
            float s = 0.f;
            #pragma unroll 8
            for (int h = 0; h < HD; h++) s = fmaf(hns[tid][h], wsc[h], s);
            s_score[tid] += s;
        }
        // loop-top gsync's __syncthreads protects shared reuse
    }

    // ===== epilogue: delta_y + score for own 8 rows (no cross-block dep)
    __syncthreads();
    const float* hlast = g_h[0];   // state after 40 steps
    for (int task = tid; task < RPB*80; task += NTHR) {
        int r  = task / 80, od = task % 80;
        int row = row0 + r;
        int k = row / NN, n = row % NN;
        int c = od / TT, tt = od % TT;
        const float* hl = hlast + row*HD;
        const float* wr = dyw + od*HD;
        float acc = dyb[od];
        #pragma unroll 8
        for (int h = 0; h < HD; h++) acc = fmaf(hl[h], wr[h], acc);
        out[((k*TT + tt)*NN + n)*2 + c] = fmaxf(acc, 0.f);
    }
    if (tid < RPB)
        out[KK*TT*NN*2 + row0 + tid] = s_score[tid] + (float)TT * bsc[0];
}

// ---------------------------------------------------------------------------
extern "C" void kernel_launch(void* const* d_in, const int* in_sizes, int n_in,
                              void* d_out, int out_size) {
    const float* hx    = (const float*)d_in[0];
    const float* cur   = (const float*)d_in[1];
    const float* ypath = (const float*)d_in[2];
    const float* img   = (const float*)d_in[3];
    const float* c1w   = (const float*)d_in[4];
    const float* c1b   = (const float*)d_in[5];
    const float* c2w   = (const float*)d_in[6];
    const float* c2b   = (const float*)d_in[7];
    const float* fvw   = (const float*)d_in[8];
    const float* fvb   = (const float*)d_in[9];
    const float* wih   = (const float*)d_in[10];
    const float* whh   = (const float*)d_in[11];
    const float* bih   = (const float*)d_in[12];
    const float* bhh   = (const float*)d_in[13];
    const float* scfw  = (const float*)d_in[14];
    const float* scfb  = (const float*)d_in[15];
    const float* wsc   = (const float*)d_in[16];
    const float* bsc   = (const float*)d_in[17];
    const float* dyw   = (const float*)d_in[18];
    const float* dyb   = (const float*)d_in[19];
    float* out = (float*)d_out;

    k_conv1<<<(16*80*80 + 255)/256, 256>>>(img, c1w, c1b);
    k_conv2<<<dim3(5, 5, 32), 256>>>(c2w, c2b);
    k_prep<<<(SEG3 + 255)/256, 256>>>(hx, wih, whh, scfw);
    k_xpre<<<(TT*NROW + 255)/256, 256>>>(ypath, cur, fvw, fvb);
    k_bins<<<(TT*NROW + 255)/256, 256>>>(ypath);
    k_steps<<<NBLK, NTHR>>>(scfb, bih, bhh, wsc, dyw, dyb, bsc, out);
}

// round 5
// speedup vs baseline: 1.6575x; 1.5098x over previous
#include <cuda_runtime.h>
#include <math.h>

#define KK 10
#define NN 96
#define TT 40
#define HD 48
#define NROW 960          // K*N
#define NBINS 36
#define NBLK 120          // persistent grid: one wave
#define RPB 8             // rows per block (120*8 = 960)
#define NTHR 256

// -------- device scratch (static allocation only) ---------------------------
__device__ __align__(16) float g_out1[16*80*80];
__device__ __align__(16) float g_fmapT[80*80*32];        // [pix][c]
__device__ __align__(16) float g_xpre[TT*NROW*48];       // [t][row][c]
__device__ int   g_nbcnt[TT*NROW];
__device__ int   g_nbbin[TT*NROW*NBINS];                  // (bin<<16)|winner
__device__ float g_nbinv[TT*NROW*NBINS];
__device__ __align__(16) float g_h[2][NROW*HD];           // double-buffered hidden
__device__ __align__(16) float g_proj[NN*1728];           // [j][bin*48+o]
__device__ __align__(16) float g_wihT[96*144];
__device__ __align__(16) float g_whhT[48*144];
__device__ __align__(16) float g_scfT[1728*48];           // [bin*48+h][o]
__device__ unsigned g_barH[TT + 1];                       // h(t) ready (12 arrivals)
__device__ unsigned g_barP[TT];                           // proj(t) ready (108 arrivals)

// -------- release/acquire barrier primitives --------------------------------
__device__ __forceinline__ void bar_arrive(unsigned* a) {
    asm volatile("red.release.gpu.global.add.u32 [%0], 1;" :: "l"(a) : "memory");
}
__device__ __forceinline__ void bar_wait(unsigned* a, unsigned tgt) {
    unsigned v;
    while (true) {
        asm volatile("ld.acquire.gpu.global.u32 %0, [%1];" : "=r"(v) : "l"(a) : "memory");
        if (v >= tgt) break;
        __nanosleep(32);
    }
}

// ---------------------------------------------------------------------------
// conv1: img (1,4,160,160) -> out1 (16,80,80), stride 2, pad 2, k=5, relu
__global__ void k_conv1(const float* __restrict__ img,
                        const float* __restrict__ w1,
                        const float* __restrict__ b1) {
    int idx = blockIdx.x * blockDim.x + threadIdx.x;
    if (idx >= 16*80*80) return;
    int ox = idx % 80;
    int oy = (idx / 80) % 80;
    int oc = idx / 6400;
    float acc = b1[oc];
    int iy0 = oy*2 - 2, ix0 = ox*2 - 2;
    for (int ic = 0; ic < 4; ic++) {
        #pragma unroll
        for (int ky = 0; ky < 5; ky++) {
            int iy = iy0 + ky;
            if ((unsigned)iy >= 160u) continue;
            #pragma unroll
            for (int kx = 0; kx < 5; kx++) {
                int ix = ix0 + kx;
                if ((unsigned)ix >= 160u) continue;
                acc = fmaf(__ldg(&img[(ic*160 + iy)*160 + ix]),
                           __ldg(&w1[((oc*4 + ic)*5 + ky)*5 + kx]), acc);
            }
        }
    }
    g_out1[idx] = fmaxf(acc, 0.f);
}

// conv2: out1 (16,80,80) -> fmapT (80*80,32), stride 1, pad 2, k=5, relu
__global__ void k_conv2(const float* __restrict__ w2,
                        const float* __restrict__ b2) {
    __shared__ float in_s[16*20*20];
    __shared__ float w_s[400];
    int oc  = blockIdx.z;
    int ty0 = blockIdx.y * 16;
    int tx0 = blockIdx.x * 16;
    int tid = threadIdx.x;

    for (int i = tid; i < 400; i += 256) w_s[i] = w2[oc*400 + i];
    for (int i = tid; i < 16*400; i += 256) {
        int ic  = i / 400;
        int rem = i % 400;
        int yy  = rem / 20, xx = rem % 20;
        int gy  = ty0 - 2 + yy, gx = tx0 - 2 + xx;
        in_s[i] = (gy >= 0 && gy < 80 && gx >= 0 && gx < 80)
                  ? g_out1[(ic*80 + gy)*80 + gx] : 0.f;
    }
    __syncthreads();

    int lx = tid % 16, ly = tid / 16;
    float acc = b2[oc];
    for (int ic = 0; ic < 16; ic++) {
        #pragma unroll
        for (int ky = 0; ky < 5; ky++) {
            #pragma unroll
            for (int kx = 0; kx < 5; kx++) {
                acc = fmaf(in_s[ic*400 + (ly + ky)*20 + (lx + kx)],
                           w_s[(ic*5 + ky)*5 + kx], acc);
            }
        }
    }
    g_fmapT[((ty0 + ly)*80 + tx0 + lx)*32 + oc] = fmaxf(acc, 0.f);
}

// ---------------------------------------------------------------------------
// fused pre-kernel: weight transposes + h0 + barrier reset | xpre | bins
#define SEG0 (1728*48)
#define SEG1 (SEG0 + 96*144)
#define SEG2 (SEG1 + 48*144)
#define SEG3 (SEG2 + NROW*HD)
#define PREP_N (SEG3 + TT + 1 + TT)
#define PREP_B ((PREP_N + 255)/256)        // 586
#define XPRE_B ((TT*NROW + 255)/256)       // 150
#define BINS_B ((TT*NROW + 255)/256)       // 150
__global__ void k_pre(const float* __restrict__ hx,
                      const float* __restrict__ wih,
                      const float* __restrict__ whh,
                      const float* __restrict__ scfw,
                      const float* __restrict__ ypath,
                      const float* __restrict__ curloc,
                      const float* __restrict__ fvw,
                      const float* __restrict__ fvb) {
    int b = blockIdx.x;
    if (b < PREP_B) {
        int i = b*256 + threadIdx.x;
        if (i < SEG0) {
            int in = i / 48, o = i % 48;
            g_scfT[i] = scfw[o*1728 + in];
        } else if (i < SEG1) {
            int j = i - SEG0;
            int c = j / 144, g = j % 144;
            g_wihT[j] = wih[g*96 + c];
        } else if (i < SEG2) {
            int j = i - SEG1;
            int c = j / 144, g = j % 144;
            g_whhT[j] = whh[g*48 + c];
        } else if (i < SEG3) {
            int j = i - SEG2;
            g_h[0][j] = hx[j % (NN*HD)];
        } else if (i < SEG3 + TT + 1) {
            g_barH[i - SEG3] = 0;
        } else if (i < PREP_N) {
            g_barP[i - SEG3 - TT - 1] = 0;
        }
        return;
    }
    if (b < PREP_B + XPRE_B) {
        int idx = (b - PREP_B)*256 + threadIdx.x;
        if (idx >= TT*NROW) return;
        int t  = idx / NROW;
        int kn = idx % NROW;
        int k  = kn / NN, n = kn % NN;
        const float* yp = ypath + ((size_t)(k*TT + t)*NN + n)*2;
        float lx = yp[0], ly = yp[1];
        int ui = 40 - (int)ly;     // trunc matches astype(int32)
        int vi = 40 - (int)lx;
        ui = min(max(ui, 0), 79);
        vi = min(max(vi, 0), 79);
        const float4* fp = (const float4*)(g_fmapT + (ui*80 + vi)*32);
        float4* xp = (float4*)(g_xpre + (size_t)idx*48);
        #pragma unroll
        for (int q = 0; q < 8; q++) xp[q] = fp[q];
        float px, py;
        if (t == 0) { px = curloc[n*2]; py = curloc[n*2 + 1]; }
        else {
            const float* pp = ypath + ((size_t)(k*TT + t - 1)*NN + n)*2;
            px = pp[0]; py = pp[1];
        }
        float vx = (lx - px) * 10.f;
        float vy = (ly - py) * 10.f;
        float* xo = g_xpre + (size_t)idx*48 + 32;
        #pragma unroll
        for (int f = 0; f < 16; f++)
            xo[f] = fmaxf(fmaf(vx, fvw[f*2], fmaf(vy, fvw[f*2 + 1], fvb[f])), 0.f);
        return;
    }
    {   // bins
        int idx = (b - PREP_B - XPRE_B)*256 + threadIdx.x;
        if (idx >= TT*NROW) return;
        int t  = idx / NROW;
        int kn = idx % NROW;
        int k  = kn / NN, i = kn % NN;
        const float* locb = ypath + (size_t)(k*TT + t)*NN*2;
        float xi = locb[i*2], yi = locb[i*2 + 1];

        const float R0f = 0.5f, R1f = 4.0f;
        const float RSTEPf = (float)((4.0 - 0.5)/6.0);
        const float TSTEPf = (float)(2.0*3.14159265358979323846/6.0);
        const float TWOPIf = (float)(2.0*3.14159265358979323846);

        int winner[NBINS];
        int cnt[NBINS];
        #pragma unroll
        for (int bb = 0; bb < NBINS; bb++) { winner[bb] = -1; cnt[bb] = 0; }

        for (int j = 0; j < NN; j++) {
            if (j == i) continue;
            float cx = locb[j*2]     - xi;
            float cy = locb[j*2 + 1] - yi;
            float dist = __fsqrt_rn(fmaf(cx, cx, cy*cy));
            if (dist < R0f || dist > R1f) continue;
            float dsafe = fmaxf(dist, 1e-10f);
            float cost  = fminf(fmaxf(__fdiv_rn(cx, dsafe), -1.f), 1.f);
            float ac    = acosf(cost);
            float theta = (cy < 0.f) ? (TWOPIf - ac) : ac;
            int ub = (int)__fdiv_rn(dist - R0f, RSTEPf);
            ub = min(max(ub, 0), 5);
            int vb = (int)__fdiv_rn(theta, TSTEPf);
            vb = min(max(vb, 0), 5);
            int bb = ub*6 + vb;
            winner[bb] = j;
            cnt[bb]++;
        }
        int nb = 0;
        int base = idx * NBINS;
        for (int bb = 0; bb < NBINS; bb++) {
            if (winner[bb] >= 0) {
                g_nbbin[base + nb] = (bb << 16) | winner[bb];
                g_nbinv[base + nb] = __fdiv_rn(1.f, (float)cnt[bb]);
                nb++;
            }
        }
        g_nbcnt[idx] = nb;
    }
}

// ---------------------------------------------------------------------------
// persistent kernel: 40 GRU steps + epilogue
__global__ void __launch_bounds__(NTHR, 1) k_steps(
        const float* __restrict__ scfb,
        const float* __restrict__ bih,
        const float* __restrict__ bhh,
        const float* __restrict__ wsc,
        const float* __restrict__ dyw,
        const float* __restrict__ dyb,
        const float* __restrict__ bsc,
        float* __restrict__ out) {
    __shared__ __align__(16) float sW[48*48];      // bin weights (loop-invariant)
    __shared__ __align__(16) float sHid[32*48];    // per-step h slice (phase A)
    __shared__ __align__(16) float xs[96][RPB];    // [c][r]
    __shared__ __align__(16) float hown[48][RPB];  // [h][r]
    __shared__ __align__(16) float gis[144][RPB];
    __shared__ __align__(16) float ghs[144][RPB];
    __shared__ __align__(16) float hns[RPB][48];
    __shared__ float s_score[RPB];

    const int tid  = threadIdx.x;
    const int blk  = blockIdx.x;
    const int row0 = blk * RPB;
    const bool isA = (blk < 108);
    const int binA  = blk / 3;
    const int partA = blk % 3;

    if (tid < RPB) s_score[tid] = 0.f;
    if (isA) {   // load bin weight once; stays resident all 40 steps
        const float4* wsrc = (const float4*)(g_scfT + binA*48*48);
        for (int i = tid; i < 576; i += NTHR)
            ((float4*)sW)[i] = wsrc[i];
    }
    // initial hown from prep's h0 (prior launch -> L1 coherent)
    for (int i = tid; i < 48*RPB; i += NTHR) {
        int h = i >> 3, r = i & 7;
        hown[h][r] = g_h[0][(row0 + r)*HD + h];
    }

    for (int t = 0; t < TT; t++) {
        const float* __restrict__ hprev = g_h[t & 1];
        float* __restrict__ hnext       = g_h[(t + 1) & 1];

        // stage lhalf (t-indexed, no cross-block dep)
        for (int i = tid; i < 48*RPB; i += NTHR) {
            int c = i >> 3, r = i & 7;
            xs[c][r] = g_xpre[(size_t)(t*NROW + row0 + r)*48 + c];
        }
        __syncthreads();   // xs lhalf + hown ready

        // gh GEMM (own rows only; independent of barriers)
        for (int task = tid; task < 288; task += NTHR) {
            int half = (task >= 144) ? 1 : 0;
            int g = task - half*144;
            float b = bhh[g];
            float4 acc = make_float4(b, b, b, b);
            #pragma unroll 4
            for (int c = 0; c < 48; c++) {
                float w = __ldg(&g_whhT[c*144 + g]);
                float4 hv = ((const float4*)(&hown[c][0]))[half];
                acc.x = fmaf(w, hv.x, acc.x);
                acc.y = fmaf(w, hv.y, acc.y);
                acc.z = fmaf(w, hv.z, acc.z);
                acc.w = fmaf(w, hv.w, acc.w);
            }
            ((float4*)(&ghs[g][0]))[half] = acc;
        }

        // ===== phase A: proj slice (blocks 0..107)
        if (isA) {
            if (t > 0 && tid == 0) bar_wait(&g_barH[t], 12);
            __syncthreads();
            const float4* hsrc = (const float4*)(hprev) + partA*384;
            for (int i = tid; i < 384; i += NTHR)
                ((float4*)sHid)[i] = __ldcg(hsrc + i);
            __syncthreads();
            for (int task = tid; task < 384; task += NTHR) {
                int j = task / 12, og = task % 12;
                const float* hp = sHid + j*48;
                float4 acc = make_float4(0.f, 0.f, 0.f, 0.f);
                #pragma unroll
                for (int h = 0; h < 48; h++) {
                    float4 w4 = *(const float4*)(sW + h*48 + og*4);
                    float hv = hp[h];
                    acc.x = fmaf(w4.x, hv, acc.x);
                    acc.y = fmaf(w4.y, hv, acc.y);
                    acc.z = fmaf(w4.z, hv, acc.z);
                    acc.w = fmaf(w4.w, hv, acc.w);
                }
                __stcg((float4*)(g_proj + (partA*32 + j)*1728 + binA*48 + og*4), acc);
            }
            __syncthreads();
            if (tid == 0) bar_arrive(&g_barP[t]);
        }

        // gi_L: lhalf contribution (independent of proj)
        for (int task = tid; task < 288; task += NTHR) {
            int half = (task >= 144) ? 1 : 0;
            int g = task - half*144;
            float b = bih[g];
            float4 acc = make_float4(b, b, b, b);
            #pragma unroll 4
            for (int c = 0; c < 48; c++) {
                float w = __ldg(&g_wihT[c*144 + g]);
                float4 xv = ((const float4*)(&xs[c][0]))[half];
                acc.x = fmaf(w, xv.x, acc.x);
                acc.y = fmaf(w, xv.y, acc.y);
                acc.z = fmaf(w, xv.z, acc.z);
                acc.w = fmaf(w, xv.w, acc.w);
            }
            ((float4*)(&gis[g][0]))[half] = acc;
        }

        if (tid == 0) bar_wait(&g_barP[t], 108);
        __syncthreads();   // proj visible (ld.cg below bypasses L1)

        // rhalf gather: (r, og) tasks, float4 over outputs
        if (tid < 96) {
            int r = tid / 12, og = tid % 12;
            int base = t*NROW + row0 + r;
            int nb = g_nbcnt[base];
            const int*   bb = g_nbbin + base*NBINS;
            const float* iv = g_nbinv + base*NBINS;
            float4 acc = *(const float4*)(scfb + og*4);
            for (int e = 0; e < nb; e++) {
                int pk    = bb[e];
                float inv = iv[e];
                int b = pk >> 16, w = pk & 0xffff;
                float4 p = __ldcg((const float4*)(g_proj + w*1728 + b*48 + og*4));
                acc.x = fmaf(inv, p.x, acc.x);
                acc.y = fmaf(inv, p.y, acc.y);
                acc.z = fmaf(inv, p.z, acc.z);
                acc.w = fmaf(inv, p.w, acc.w);
            }
            xs[48 + og*4 + 0][r] = fmaxf(acc.x, 0.f);
            xs[48 + og*4 + 1][r] = fmaxf(acc.y, 0.f);
            xs[48 + og*4 + 2][r] = fmaxf(acc.z, 0.f);
            xs[48 + og*4 + 3][r] = fmaxf(acc.w, 0.f);
        }
        __syncthreads();

        // gi_R: rhalf contribution
        for (int task = tid; task < 288; task += NTHR) {
            int half = (task >= 144) ? 1 : 0;
            int g = task - half*144;
            float4 acc = ((const float4*)(&gis[g][0]))[half];
            #pragma unroll 4
            for (int c = 48; c < 96; c++) {
                float w = __ldg(&g_wihT[c*144 + g]);
                float4 xv = ((const float4*)(&xs[c][0]))[half];
                acc.x = fmaf(w, xv.x, acc.x);
                acc.y = fmaf(w, xv.y, acc.y);
                acc.z = fmaf(w, xv.z, acc.z);
                acc.w = fmaf(w, xv.w, acc.w);
            }
            ((float4*)(&gis[g][0]))[half] = acc;
        }
        __syncthreads();

        // GRU elementwise
        for (int task = tid; task < RPB*48; task += NTHR) {
            int r = task / 48, o = task % 48;
            float gir = gis[o][r],      ghr = ghs[o][r];
            float giz = gis[48 + o][r], ghz = ghs[48 + o][r];
            float gin = gis[96 + o][r], ghn = ghs[96 + o][r];
            float rg = 1.f / (1.f + expf(-(gir + ghr)));
            float zg = 1.f / (1.f + expf(-(giz + ghz)));
            float ng = tanhf(fmaf(rg, ghn, gin));
            float hold = hown[o][r];
            float hn = fmaf(zg, hold, (1.f - zg)*ng);
            hnext[(row0 + r)*HD + o] = hn;
            hns[r][o] = hn;
        }
        __syncthreads();
        if (blk < 12 && tid == 0) bar_arrive(&g_barH[t + 1]);

        if (tid < RPB) {
            float s = 0.f;
            #pragma unroll 8
            for (int h = 0; h < HD; h++) s = fmaf(hns[tid][h], wsc[h], s);
            s_score[tid] += s;
        }
        // refresh hown from hns (h stays on-chip)
        for (int i = tid; i < 48*RPB; i += NTHR) {
            int h = i >> 3, r = i & 7;
            hown[h][r] = hns[r][h];
        }
        __syncthreads();
    }

    // epilogue: own rows only (own writes -> no barrier needed)
    const float* hlast = g_h[0];
    for (int task = tid; task < RPB*80; task += NTHR) {
        int r  = task / 80, od = task % 80;
        int row = row0 + r;
        int k = row / NN, n = row % NN;
        int c = od / TT, tt = od % TT;
        const float* hl = hlast + row*HD;
        const float* wr = dyw + od*HD;
        float acc = dyb[od];
        #pragma unroll 8
        for (int h = 0; h < HD; h++) acc = fmaf(hl[h], wr[h], acc);
        out[((k*TT + tt)*NN + n)*2 + c] = fmaxf(acc, 0.f);
    }
    if (tid < RPB)
        out[KK*TT*NN*2 + row0 + tid] = s_score[tid] + (float)TT * bsc[0];
}

// ---------------------------------------------------------------------------
extern "C" void kernel_launch(void* const* d_in, const int* in_sizes, int n_in,
                              void* d_out, int out_size) {
    const float* hx    = (const float*)d_in[0];
    const float* cur   = (const float*)d_in[1];
    const float* ypath = (const float*)d_in[2];
    const float* img   = (const float*)d_in[3];
    const float* c1w   = (const float*)d_in[4];
    const float* c1b   = (const float*)d_in[5];
    const float* c2w   = (const float*)d_in[6];
    const float* c2b   = (const float*)d_in[7];
    const float* fvw   = (const float*)d_in[8];
    const float* fvb   = (const float*)d_in[9];
    const float* wih   = (const float*)d_in[10];
    const float* whh   = (const float*)d_in[11];
    const float* bih   = (const float*)d_in[12];
    const float* bhh   = (const float*)d_in[13];
    const float* scfw  = (const float*)d_in[14];
    const float* scfb  = (const float*)d_in[15];
    const float* wsc   = (const float*)d_in[16];
    const float* bsc   = (const float*)d_in[17];
    const float* dyw   = (const float*)d_in[18];
    const float* dyb   = (const float*)d_in[19];
    float* out = (float*)d_out;

    k_conv1<<<(16*80*80 + 255)/256, 256>>>(img, c1w, c1b);
    k_conv2<<<dim3(5, 5, 32), 256>>>(c2w, c2b);
    k_pre<<<PREP_B + XPRE_B + BINS_B, 256>>>(hx, wih, whh, scfw,
                                             ypath, cur, fvw, fvb);
    k_steps<<<NBLK, NTHR>>>(scfb, bih, bhh, wsc, dyw, dyb, bsc, out);
}

// round 6
// speedup vs baseline: 1.6701x; 1.0076x over previous
#include <cuda_runtime.h>
#include <math.h>

#define KK 10
#define NN 96
#define TT 40
#define HD 48
#define NROW 960          // K*N
#define NBINS 36
#define NBLK 120          // 12 leader blocks + 108 proj/follower blocks
#define RPB 8             // rows per block (120*8 = 960)
#define NTHR 256

// -------- device scratch (static allocation only) ---------------------------
__device__ __align__(16) float g_out1[16*80*80];
__device__ __align__(16) float g_fmapT[80*80*32];        // [pix][c]
__device__ __align__(16) float g_xpre[TT*NROW*48];       // [t][row][c]
__device__ int   g_nbcnt[TT*NROW];
__device__ int   g_nbbin[TT*NROW*NBINS];                  // (bin<<16)|winner
__device__ float g_nbinv[TT*NROW*NBINS];
__device__ __align__(16) float g_h0[2][NN*HD];            // recurrent pool state (k=0)
__device__ __align__(16) float g_proj[2][NN*1728];        // parity double buffer
__device__ __align__(16) float g_wihT[96*144];
__device__ __align__(16) float g_whhT[48*144];
__device__ __align__(16) float g_scfT[1728*48];           // [bin*48+h][o]
__device__ unsigned g_barHp[3*(TT + 1)];                  // h0 part flags (4 arrivals)
__device__ unsigned g_barP[TT];                           // proj ready (108 arrivals)

// -------- release/acquire primitives ----------------------------------------
__device__ __forceinline__ void bar_arrive(unsigned* a) {
    asm volatile("red.release.gpu.global.add.u32 [%0], 1;" :: "l"(a) : "memory");
}
__device__ __forceinline__ void bar_wait(unsigned* a, unsigned tgt) {
    unsigned v;
    while (true) {
        asm volatile("ld.acquire.gpu.global.u32 %0, [%1];" : "=r"(v) : "l"(a) : "memory");
        if (v >= tgt) break;
        __nanosleep(32);
    }
}

// ---------------------------------------------------------------------------
// conv1: img (1,4,160,160) -> out1 (16,80,80), stride 2, pad 2, k=5, relu
__global__ void k_conv1(const float* __restrict__ img,
                        const float* __restrict__ w1,
                        const float* __restrict__ b1) {
    int idx = blockIdx.x * blockDim.x + threadIdx.x;
    if (idx >= 16*80*80) return;
    int ox = idx % 80;
    int oy = (idx / 80) % 80;
    int oc = idx / 6400;
    float acc = b1[oc];
    int iy0 = oy*2 - 2, ix0 = ox*2 - 2;
    for (int ic = 0; ic < 4; ic++) {
        #pragma unroll
        for (int ky = 0; ky < 5; ky++) {
            int iy = iy0 + ky;
            if ((unsigned)iy >= 160u) continue;
            #pragma unroll
            for (int kx = 0; kx < 5; kx++) {
                int ix = ix0 + kx;
                if ((unsigned)ix >= 160u) continue;
                acc = fmaf(__ldg(&img[(ic*160 + iy)*160 + ix]),
                           __ldg(&w1[((oc*4 + ic)*5 + ky)*5 + kx]), acc);
            }
        }
    }
    g_out1[idx] = fmaxf(acc, 0.f);
}

// conv2: out1 (16,80,80) -> fmapT (80*80,32), stride 1, pad 2, k=5, relu
__global__ void k_conv2(const float* __restrict__ w2,
                        const float* __restrict__ b2) {
    __shared__ float in_s[16*20*20];
    __shared__ float w_s[400];
    int oc  = blockIdx.z;
    int ty0 = blockIdx.y * 16;
    int tx0 = blockIdx.x * 16;
    int tid = threadIdx.x;

    for (int i = tid; i < 400; i += 256) w_s[i] = w2[oc*400 + i];
    for (int i = tid; i < 16*400; i += 256) {
        int ic  = i / 400;
        int rem = i % 400;
        int yy  = rem / 20, xx = rem % 20;
        int gy  = ty0 - 2 + yy, gx = tx0 - 2 + xx;
        in_s[i] = (gy >= 0 && gy < 80 && gx >= 0 && gx < 80)
                  ? g_out1[(ic*80 + gy)*80 + gx] : 0.f;
    }
    __syncthreads();

    int lx = tid % 16, ly = tid / 16;
    float acc = b2[oc];
    for (int ic = 0; ic < 16; ic++) {
        #pragma unroll
        for (int ky = 0; ky < 5; ky++) {
            #pragma unroll
            for (int kx = 0; kx < 5; kx++) {
                acc = fmaf(in_s[ic*400 + (ly + ky)*20 + (lx + kx)],
                           w_s[(ic*5 + ky)*5 + kx], acc);
            }
        }
    }
    g_fmapT[((ty0 + ly)*80 + tx0 + lx)*32 + oc] = fmaxf(acc, 0.f);
}

// ---------------------------------------------------------------------------
// fused pre-kernel: weight transposes + h0 + barrier reset | xpre | bins
#define SEG0 (1728*48)
#define SEG1 (SEG0 + 96*144)
#define SEG2 (SEG1 + 48*144)
#define SEG3 (SEG2 + NN*HD)
#define PREP_N (SEG3 + 3*(TT + 1) + TT)
#define PREP_B ((PREP_N + 255)/256)
#define XPRE_B ((TT*NROW + 255)/256)
#define BINS_B ((TT*NROW + 255)/256)
__global__ void k_pre(const float* __restrict__ hx,
                      const float* __restrict__ wih,
                      const float* __restrict__ whh,
                      const float* __restrict__ scfw,
                      const float* __restrict__ ypath,
                      const float* __restrict__ curloc,
                      const float* __restrict__ fvw,
                      const float* __restrict__ fvb) {
    int b = blockIdx.x;
    if (b < PREP_B) {
        int i = b*256 + threadIdx.x;
        if (i < SEG0) {
            int in = i / 48, o = i % 48;
            g_scfT[i] = scfw[o*1728 + in];
        } else if (i < SEG1) {
            int j = i - SEG0;
            int c = j / 144, g = j % 144;
            g_wihT[j] = wih[g*96 + c];
        } else if (i < SEG2) {
            int j = i - SEG1;
            int c = j / 144, g = j % 144;
            g_whhT[j] = whh[g*48 + c];
        } else if (i < SEG3) {
            g_h0[0][i - SEG2] = hx[i - SEG2];
        } else if (i < SEG3 + 3*(TT + 1)) {
            g_barHp[i - SEG3] = 0;
        } else if (i < PREP_N) {
            g_barP[i - SEG3 - 3*(TT + 1)] = 0;
        }
        return;
    }
    if (b < PREP_B + XPRE_B) {
        int idx = (b - PREP_B)*256 + threadIdx.x;
        if (idx >= TT*NROW) return;
        int t  = idx / NROW;
        int kn = idx % NROW;
        int k  = kn / NN, n = kn % NN;
        const float* yp = ypath + ((size_t)(k*TT + t)*NN + n)*2;
        float lx = yp[0], ly = yp[1];
        int ui = 40 - (int)ly;     // trunc matches astype(int32)
        int vi = 40 - (int)lx;
        ui = min(max(ui, 0), 79);
        vi = min(max(vi, 0), 79);
        const float4* fp = (const float4*)(g_fmapT + (ui*80 + vi)*32);
        float4* xp = (float4*)(g_xpre + (size_t)idx*48);
        #pragma unroll
        for (int q = 0; q < 8; q++) xp[q] = fp[q];
        float px, py;
        if (t == 0) { px = curloc[n*2]; py = curloc[n*2 + 1]; }
        else {
            const float* pp = ypath + ((size_t)(k*TT + t - 1)*NN + n)*2;
            px = pp[0]; py = pp[1];
        }
        float vx = (lx - px) * 10.f;
        float vy = (ly - py) * 10.f;
        float* xo = g_xpre + (size_t)idx*48 + 32;
        #pragma unroll
        for (int f = 0; f < 16; f++)
            xo[f] = fmaxf(fmaf(vx, fvw[f*2], fmaf(vy, fvw[f*2 + 1], fvb[f])), 0.f);
        return;
    }
    {   // bins
        int idx = (b - PREP_B - XPRE_B)*256 + threadIdx.x;
        if (idx >= TT*NROW) return;
        int t  = idx / NROW;
        int kn = idx % NROW;
        int k  = kn / NN, i = kn % NN;
        const float* locb = ypath + (size_t)(k*TT + t)*NN*2;
        float xi = locb[i*2], yi = locb[i*2 + 1];

        const float R0f = 0.5f, R1f = 4.0f;
        const float RSTEPf = (float)((4.0 - 0.5)/6.0);
        const float TSTEPf = (float)(2.0*3.14159265358979323846/6.0);
        const float TWOPIf = (float)(2.0*3.14159265358979323846);

        int winner[NBINS];
        int cnt[NBINS];
        #pragma unroll
        for (int bb = 0; bb < NBINS; bb++) { winner[bb] = -1; cnt[bb] = 0; }

        for (int j = 0; j < NN; j++) {
            if (j == i) continue;
            float cx = locb[j*2]     - xi;
            float cy = locb[j*2 + 1] - yi;
            float dist = __fsqrt_rn(fmaf(cx, cx, cy*cy));
            if (dist < R0f || dist > R1f) continue;
            float dsafe = fmaxf(dist, 1e-10f);
            float cost  = fminf(fmaxf(__fdiv_rn(cx, dsafe), -1.f), 1.f);
            float ac    = acosf(cost);
            float theta = (cy < 0.f) ? (TWOPIf - ac) : ac;
            int ub = (int)__fdiv_rn(dist - R0f, RSTEPf);
            ub = min(max(ub, 0), 5);
            int vb = (int)__fdiv_rn(theta, TSTEPf);
            vb = min(max(vb, 0), 5);
            int bb = ub*6 + vb;
            winner[bb] = j;
            cnt[bb]++;
        }
        int nb = 0;
        int base = idx * NBINS;
        for (int bb = 0; bb < NBINS; bb++) {
            if (winner[bb] >= 0) {
                g_nbbin[base + nb] = (bb << 16) | winner[bb];
                g_nbinv[base + nb] = __fdiv_rn(1.f, (float)cnt[bb]);
                nb++;
            }
        }
        g_nbcnt[idx] = nb;
    }
}

// ---------------------------------------------------------------------------
// persistent kernel: 40 GRU steps + epilogue
__global__ void __launch_bounds__(NTHR, 1) k_steps(
        const float* __restrict__ scfb,
        const float* __restrict__ bih,
        const float* __restrict__ bhh,
        const float* __restrict__ wsc,
        const float* __restrict__ dyw,
        const float* __restrict__ dyb,
        const float* __restrict__ bsc,
        float* __restrict__ out) {
    __shared__ __align__(16) float sW[48*48];      // bin weights (A-blocks, loop-invariant)
    __shared__ __align__(16) float sHid[32*48];    // h0 slice (A-blocks)
    __shared__ __align__(16) float xs[96][RPB];    // [c][r]
    __shared__ __align__(16) float hown[48][RPB];  // [h][r]  (persistent local h)
    __shared__ __align__(16) float gis[144][RPB];
    __shared__ __align__(16) float ghs[144][RPB];
    __shared__ __align__(16) float hns[RPB][48];
    __shared__ int   s_off[RPB][NBINS];             // proj float-offset per entry
    __shared__ float s_inv[RPB][NBINS];
    __shared__ int   s_nb[RPB];
    __shared__ float s_score[RPB];

    const int tid  = threadIdx.x;
    const int blk  = blockIdx.x;
    const int row0 = blk * RPB;
    const bool lead = (blk < 12);          // rows 0-95: recurrent pool producers
    const int binA  = (blk - 12) / 3;      // A-role for blk>=12
    const int partA = (blk - 12) % 3;

    if (tid < RPB) s_score[tid] = 0.f;
    if (!lead) {   // bin weight resident in smem for all 40 steps
        const float4* wsrc = (const float4*)(g_scfT + binA*48*48);
        for (int i = tid; i < 576; i += NTHR)
            ((float4*)sW)[i] = wsrc[i];
    }
    // initial local hidden: tile(hx) -> row (row0+r) uses h0 row (row0+r)%96
    for (int i = tid; i < 48*RPB; i += NTHR) {
        int h = i >> 3, r = i & 7;
        hown[h][r] = g_h0[0][((row0 + r) % NN)*HD + h];
    }

    for (int t = 0; t < TT; t++) {
        const int par  = t & 1;
        const float* __restrict__ projR = g_proj[par];

        // ---- stage (off critical path): lhalf + gather metadata
        for (int i = tid; i < 48*RPB; i += NTHR) {
            int c = i >> 3, r = i & 7;
            xs[c][r] = g_xpre[(size_t)(t*NROW + row0 + r)*48 + c];
        }
        if (tid < RPB) s_nb[tid] = g_nbcnt[t*NROW + row0 + tid];
        for (int i = tid; i < RPB*NBINS; i += NTHR) {
            int r = i / NBINS, e = i % NBINS;
            int pk = g_nbbin[(t*NROW + row0 + r)*NBINS + e];
            s_off[r][e] = (pk & 0xffff)*1728 + (pk >> 16)*48;
            s_inv[r][e] = g_nbinv[(t*NROW + row0 + r)*NBINS + e];
        }
        __syncthreads();

        // ---- A-blocks: proj slice first (this is the global critical path)
        if (!lead) {
            if (t > 0) bar_wait(&g_barHp[partA*(TT + 1) + t], 4);
            const float4* hsrc = (const float4*)(g_h0[par]) + partA*384;
            for (int i = tid; i < 384; i += NTHR) {
                float4 v = __ldcg(hsrc + i);
                ((float4*)sHid)[i] = v;
            }
            __syncthreads();
            float* projW = g_proj[par];   // same parity buffer being built
            for (int task = tid; task < 384; task += NTHR) {
                int j = task / 12, og = task % 12;
                const float* hp = sHid + j*48;
                float4 acc = make_float4(0.f, 0.f, 0.f, 0.f);
                #pragma unroll
                for (int h = 0; h < 48; h++) {
                    float4 w4 = *(const float4*)(sW + h*48 + og*4);
                    float hv = hp[h];
                    acc.x = fmaf(w4.x, hv, acc.x);
                    acc.y = fmaf(w4.y, hv, acc.y);
                    acc.z = fmaf(w4.z, hv, acc.z);
                    acc.w = fmaf(w4.w, hv, acc.w);
                }
                __stcg((float4*)(projW + (partA*32 + j)*1728 + binA*48 + og*4), acc);
            }
            __threadfence();
            __syncthreads();
            if (tid == 0) bar_arrive(&g_barP[t]);
        }

        // ---- local work independent of proj: gh + gi_L
        for (int task = tid; task < 288; task += NTHR) {
            int half = (task >= 144) ? 1 : 0;
            int g = task - half*144;
            float b = bhh[g];
            float4 acc = make_float4(b, b, b, b);
            #pragma unroll 4
            for (int c = 0; c < 48; c++) {
                float w = __ldg(&g_whhT[c*144 + g]);
                float4 hv = ((const float4*)(&hown[c][0]))[half];
                acc.x = fmaf(w, hv.x, acc.x);
                acc.y = fmaf(w, hv.y, acc.y);
                acc.z = fmaf(w, hv.z, acc.z);
                acc.w = fmaf(w, hv.w, acc.w);
            }
            ((float4*)(&ghs[g][0]))[half] = acc;
        }
        for (int task = tid; task < 288; task += NTHR) {
            int half = (task >= 144) ? 1 : 0;
            int g = task - half*144;
            float b = bih[g];
            float4 acc = make_float4(b, b, b, b);
            #pragma unroll 4
            for (int c = 0; c < 48; c++) {
                float w = __ldg(&g_wihT[c*144 + g]);
                float4 xv = ((const float4*)(&xs[c][0]))[half];
                acc.x = fmaf(w, xv.x, acc.x);
                acc.y = fmaf(w, xv.y, acc.y);
                acc.z = fmaf(w, xv.z, acc.z);
                acc.w = fmaf(w, xv.w, acc.w);
            }
            ((float4*)(&gis[g][0]))[half] = acc;
        }

        // ---- wait proj complete (all warps poll; coalesced acquire loads)
        bar_wait(&g_barP[t], 108);

        // ---- rhalf gather, MLP-batched (threads 0..95: r=tid/12, og=tid%12)
        if (tid < 96) {
            int r = tid / 12, og = tid % 12;
            int nb = s_nb[r];
            float4 acc = *(const float4*)(scfb + og*4);
            for (int base = 0; base < nb; base += 8) {
                float4 pv[8];
                float  iv[8];
                #pragma unroll
                for (int e = 0; e < 8; e++) {
                    int idx = base + e;
                    if (idx < nb) {
                        pv[e] = __ldcg((const float4*)(projR + s_off[r][idx]) + og);
                        iv[e] = s_inv[r][idx];
                    }
                }
                #pragma unroll
                for (int e = 0; e < 8; e++) {
                    if (base + e < nb) {
                        acc.x = fmaf(iv[e], pv[e].x, acc.x);
                        acc.y = fmaf(iv[e], pv[e].y, acc.y);
                        acc.z = fmaf(iv[e], pv[e].z, acc.z);
                        acc.w = fmaf(iv[e], pv[e].w, acc.w);
                    }
                }
            }
            xs[48 + og*4 + 0][r] = fmaxf(acc.x, 0.f);
            xs[48 + og*4 + 1][r] = fmaxf(acc.y, 0.f);
            xs[48 + og*4 + 2][r] = fmaxf(acc.z, 0.f);
            xs[48 + og*4 + 3][r] = fmaxf(acc.w, 0.f);
        }
        __syncthreads();

        // ---- gi_R: rhalf contribution
        for (int task = tid; task < 288; task += NTHR) {
            int half = (task >= 144) ? 1 : 0;
            int g = task - half*144;
            float4 acc = ((const float4*)(&gis[g][0]))[half];
            #pragma unroll 4
            for (int c = 48; c < 96; c++) {
                float w = __ldg(&g_wihT[c*144 + g]);
                float4 xv = ((const float4*)(&xs[c][0]))[half];
                acc.x = fmaf(w, xv.x, acc.x);
                acc.y = fmaf(w, xv.y, acc.y);
                acc.z = fmaf(w, xv.z, acc.z);
                acc.w = fmaf(w, xv.w, acc.w);
            }
            ((float4*)(&gis[g][0]))[half] = acc;
        }
        __syncthreads();

        // ---- GRU elementwise; leaders publish h0(t+1) to L2
        float* h0next = g_h0[par ^ 1];
        for (int task = tid; task < RPB*48; task += NTHR) {
            int r = task / 48, o = task % 48;
            float gir = gis[o][r],      ghr = ghs[o][r];
            float giz = gis[48 + o][r], ghz = ghs[48 + o][r];
            float gin = gis[96 + o][r], ghn = ghs[96 + o][r];
            float rg = 1.f / (1.f + expf(-(gir + ghr)));
            float zg = 1.f / (1.f + expf(-(giz + ghz)));
            float ng = tanhf(fmaf(rg, ghn, gin));
            float hold = hown[o][r];
            float hn = fmaf(zg, hold, (1.f - zg)*ng);
            hns[r][o] = hn;
            hown[o][r] = hn;
            if (lead) __stcg(&h0next[(row0 + r)*HD + o], hn);
        }
        if (lead) __threadfence();
        __syncthreads();
        if (lead && tid == 0 && t + 1 < TT)
            bar_arrive(&g_barHp[(blk >> 2)*(TT + 1) + t + 1]);

        if (tid < RPB) {
            float s = 0.f;
            #pragma unroll 8
            for (int h = 0; h < HD; h++) s = fmaf(hns[tid][h], wsc[h], s);
            s_score[tid] += s;
        }
        // next loop-top __syncthreads protects xs/metadata reuse
    }

    // ---- epilogue: own rows only (h kept local in hown)
    __syncthreads();
    for (int task = tid; task < RPB*80; task += NTHR) {
        int r  = task / 80, od = task % 80;
        int row = row0 + r;
        int k = row / NN, n = row % NN;
        int c = od / TT, tt = od % TT;
        const float* wr = dyw + od*HD;
        float acc = dyb[od];
        #pragma unroll 8
        for (int h = 0; h < HD; h++) acc = fmaf(hown[h][r], wr[h], acc);
        out[((k*TT + tt)*NN + n)*2 + c] = fmaxf(acc, 0.f);
    }
    if (tid < RPB)
        out[KK*TT*NN*2 + row0 + tid] = s_score[tid] + (float)TT * bsc[0];
}

// ---------------------------------------------------------------------------
extern "C" void kernel_launch(void* const* d_in, const int* in_sizes, int n_in,
                              void* d_out, int out_size) {
    const float* hx    = (const float*)d_in[0];
    const float* cur   = (const float*)d_in[1];
    const float* ypath = (const float*)d_in[2];
    const float* img   = (const float*)d_in[3];
    const float* c1w   = (const float*)d_in[4];
    const float* c1b   = (const float*)d_in[5];
    const float* c2w   = (const float*)d_in[6];
    const float* c2b   = (const float*)d_in[7];
    const float* fvw   = (const float*)d_in[8];
    const float* fvb   = (const float*)d_in[9];
    const float* wih   = (const float*)d_in[10];
    const float* whh   = (const float*)d_in[11];
    const float* bih   = (const float*)d_in[12];
    const float* bhh   = (const float*)d_in[13];
    const float* scfw  = (const float*)d_in[14];
    const float* scfb  = (const float*)d_in[15];
    const float* wsc   = (const float*)d_in[16];
    const float* bsc   = (const float*)d_in[17];
    const float* dyw   = (const float*)d_in[18];
    const float* dyb   = (const float*)d_in[19];
    float* out = (float*)d_out;

    k_conv1<<<(16*80*80 + 255)/256, 256>>>(img, c1w, c1b);
    k_conv2<<<dim3(5, 5, 32), 256>>>(c2w, c2b);
    k_pre<<<PREP_B + XPRE_B + BINS_B, 256>>>(hx, wih, whh, scfw,
                                             ypath, cur, fvw, fvb);
    k_steps<<<NBLK, NTHR>>>(scfb, bih, bhh, wsc, dyw, dyb, bsc, out);
}